// round 2
// baseline (speedup 1.0000x reference)
#include <cuda_runtime.h>

#define THREADS 256

// Soft-tree node: w*min(a,b) + (1-w)*max(a,b) == max(a,b) - w*|a-b|
// Compiles to FADD + FMNMX + FFMA (neg/abs as source modifiers).
__device__ __forceinline__ float node(float a, float b, float w) {
    return fmaf(w, -fabsf(a - b), fmaxf(a, b));
}

__global__ void __launch_bounds__(THREADS)
bacon_forest_kernel(const float* __restrict__ c20,
                    const float* __restrict__ w_raw,
                    float* __restrict__ out,
                    int B)
{
    // sigmoid(w_raw), rows padded to 20 floats so each row supports float4 LDS.
    __shared__ float sw[19 * 20];
    for (int i = threadIdx.x; i < 19 * 20; i += THREADS) {
        int r = i / 20;
        int c = i - r * 20;
        float v = 0.0f;
        if (c < 19) {
            float raw = __ldg(&w_raw[r * 19 + c]);
            v = 1.0f / (1.0f + __expf(-raw));
        }
        sw[i] = v;
    }
    __syncthreads();

    int b = blockIdx.x * THREADS + threadIdx.x;
    if (b >= B) return;

    // 20 inputs via 5x LDG.128 (rows are 80B, 16B-aligned).
    const float4* cp = reinterpret_cast<const float4*>(c20) + (size_t)b * 5;
    float4 q0 = cp[0], q1 = cp[1], q2 = cp[2], q3 = cp[3], q4 = cp[4];
    float x[20] = { q0.x, q0.y, q0.z, q0.w,  q1.x, q1.y, q1.z, q1.w,
                    q2.x, q2.y, q2.z, q2.w,  q3.x, q3.y, q3.z, q3.w,
                    q4.x, q4.y, q4.z, q4.w };

    // Layer-0 inputs are identical for all 19 trees: hoist max/|diff| pairs.
    float m0[10], d0[10];
    #pragma unroll
    for (int j = 0; j < 10; ++j) {
        float a = x[2 * j], bb = x[2 * j + 1];
        m0[j] = fmaxf(a, bb);
        d0[j] = fabsf(a - bb);
    }

    float* op = out + (size_t)b * 19;

    #pragma unroll 1
    for (int t = 0; t < 19; ++t) {
        // One tree's 19 weights via 5x LDS.128 (warp-uniform broadcast).
        const float4* wp = reinterpret_cast<const float4*>(&sw[t * 20]);
        float4 w0 = wp[0], w1 = wp[1], w2 = wp[2], w3 = wp[3], w4 = wp[4];

        // Layer 0 (20 -> 10): invariants precomputed, one FFMA per node.
        float y0 = fmaf(w0.x, -d0[0], m0[0]);
        float y1 = fmaf(w0.y, -d0[1], m0[1]);
        float y2 = fmaf(w0.z, -d0[2], m0[2]);
        float y3 = fmaf(w0.w, -d0[3], m0[3]);
        float y4 = fmaf(w1.x, -d0[4], m0[4]);
        float y5 = fmaf(w1.y, -d0[5], m0[5]);
        float y6 = fmaf(w1.z, -d0[6], m0[6]);
        float y7 = fmaf(w1.w, -d0[7], m0[7]);
        float y8 = fmaf(w2.x, -d0[8], m0[8]);
        float y9 = fmaf(w2.y, -d0[9], m0[9]);

        // Layer 1 (10 -> 5): weights cols 10..14
        float z0 = node(y0, y1, w2.z);
        float z1 = node(y2, y3, w2.w);
        float z2 = node(y4, y5, w3.x);
        float z3 = node(y6, y7, w3.y);
        float z4 = node(y8, y9, w3.z);

        // Layer 2 (5 -> 2, carry z4): cols 15,16
        float u0 = node(z0, z1, w3.w);
        float u1 = node(z2, z3, w4.x);

        // Layer 3 (3 -> 1, carry u2=z4): col 17
        float v0 = node(u0, u1, w4.y);

        // Layer 4 (2 -> 1): col 18
        float o = node(v0, z4, w4.z);

        o = fminf(fmaxf(o, 1e-6f), 1.0f - 1e-6f);
        op[t] = o;
    }
}

extern "C" void kernel_launch(void* const* d_in, const int* in_sizes, int n_in,
                              void* d_out, int out_size) {
    // metadata order: p1 (int32), p2 (int32), c20 (float32, B*20), w_raw (float32, 361)
    const float* c20   = (const float*)d_in[2];
    const float* w_raw = (const float*)d_in[3];
    float* out = (float*)d_out;
    int B = in_sizes[2] / 20;
    int grid = (B + THREADS - 1) / THREADS;
    bacon_forest_kernel<<<grid, THREADS>>>(c20, w_raw, out, B);
}

// round 3
// speedup vs baseline: 1.2147x; 1.2147x over previous
#include <cuda_runtime.h>

#define THREADS 256

// Soft-tree node: w*min(a,b) + (1-w)*max(a,b) == max(a,b) - w*|a-b|
// FADD + FMNMX + FFMA (neg/abs fold into source modifiers).
__device__ __forceinline__ float node(float a, float b, float w) {
    return fmaf(w, -fabsf(a - b), fmaxf(a, b));
}

__global__ void __launch_bounds__(THREADS)
bacon_forest_kernel(const float* __restrict__ c20,
                    const float* __restrict__ w_raw,
                    float* __restrict__ out,
                    int B)
{
    // sigmoid(w_raw); rows padded to 20 floats so each row supports LDS.128.
    __shared__ __align__(16) float sw[19 * 20];
    // Output staging: thread-private row of 19 (stride 19 odd => STS conflict-free).
    __shared__ __align__(16) float obuf[THREADS * 19];

    for (int i = threadIdx.x; i < 19 * 20; i += THREADS) {
        int r = i / 20;
        int c = i - r * 20;
        float v = 0.0f;
        if (c < 19) {
            float raw = __ldg(&w_raw[r * 19 + c]);
            v = 1.0f / (1.0f + __expf(-raw));
        }
        sw[i] = v;
    }
    __syncthreads();

    const int tid  = threadIdx.x;
    const int base = blockIdx.x * THREADS;
    const int b    = base + tid;

    if (b < B) {
        // 20 inputs via 5x LDG.128 (rows are 80B, 16B-aligned).
        const float4* cp = reinterpret_cast<const float4*>(c20) + (size_t)b * 5;
        float4 q0 = cp[0], q1 = cp[1], q2 = cp[2], q3 = cp[3], q4 = cp[4];
        float x[20] = { q0.x, q0.y, q0.z, q0.w,  q1.x, q1.y, q1.z, q1.w,
                        q2.x, q2.y, q2.z, q2.w,  q3.x, q3.y, q3.z, q3.w,
                        q4.x, q4.y, q4.z, q4.w };

        // Layer-0 inputs identical for all 19 trees: hoist max/|diff| pairs.
        float m0[10], d0[10];
        #pragma unroll
        for (int j = 0; j < 10; ++j) {
            float a = x[2 * j], bb = x[2 * j + 1];
            m0[j] = fmaxf(a, bb);
            d0[j] = fabsf(a - bb);
        }

        float* orow = &obuf[tid * 19];

        #pragma unroll 1
        for (int t = 0; t < 19; ++t) {
            // Tree's 19 weights via 5x LDS.128 (uniform address => broadcast).
            const float4* wp = reinterpret_cast<const float4*>(&sw[t * 20]);
            float4 w0 = wp[0], w1 = wp[1], w2 = wp[2], w3 = wp[3], w4 = wp[4];

            // Layer 0 (20 -> 10): one FFMA per node using hoisted invariants.
            float y0 = fmaf(w0.x, -d0[0], m0[0]);
            float y1 = fmaf(w0.y, -d0[1], m0[1]);
            float y2 = fmaf(w0.z, -d0[2], m0[2]);
            float y3 = fmaf(w0.w, -d0[3], m0[3]);
            float y4 = fmaf(w1.x, -d0[4], m0[4]);
            float y5 = fmaf(w1.y, -d0[5], m0[5]);
            float y6 = fmaf(w1.z, -d0[6], m0[6]);
            float y7 = fmaf(w1.w, -d0[7], m0[7]);
            float y8 = fmaf(w2.x, -d0[8], m0[8]);
            float y9 = fmaf(w2.y, -d0[9], m0[9]);

            // Layer 1 (10 -> 5): cols 10..14
            float z0 = node(y0, y1, w2.z);
            float z1 = node(y2, y3, w2.w);
            float z2 = node(y4, y5, w3.x);
            float z3 = node(y6, y7, w3.y);
            float z4 = node(y8, y9, w3.z);

            // Layer 2 (5 -> 2, carry z4): cols 15,16
            float u0 = node(z0, z1, w3.w);
            float u1 = node(z2, z3, w4.x);

            // Layer 3 (3 -> 1, carry z4): col 17
            float v0 = node(u0, u1, w4.y);

            // Layer 4 (2 -> 1): col 18
            float o = node(v0, z4, w4.z);

            o = fminf(fmaxf(o, 1e-6f), 1.0f - 1e-6f);
            orow[t] = o;
        }
    }
    __syncthreads();

    // Coalesced block-wide writeback. Block's out region is contiguous:
    // [base*19, (base+nS)*19) floats; base multiple of 256 => 16B-aligned.
    const int nS     = min(THREADS, B - base);
    const int nFlt   = nS * 19;
    const int nVec   = nFlt >> 2;
    float*        og = out + (size_t)base * 19;
    float4*       o4 = reinterpret_cast<float4*>(og);
    const float4* s4 = reinterpret_cast<const float4*>(obuf);

    for (int i = tid; i < nVec; i += THREADS)
        o4[i] = s4[i];                       // LDS.128 conflict-free + STG.128 coalesced
    for (int i = (nVec << 2) + tid; i < nFlt; i += THREADS)
        og[i] = obuf[i];                     // remainder (empty for nS % 4 == 0)
}

extern "C" void kernel_launch(void* const* d_in, const int* in_sizes, int n_in,
                              void* d_out, int out_size) {
    // metadata order: p1 (int32), p2 (int32), c20 (float32, B*20), w_raw (float32, 361)
    const float* c20   = (const float*)d_in[2];
    const float* w_raw = (const float*)d_in[3];
    float* out = (float*)d_out;
    int B = in_sizes[2] / 20;
    int grid = (B + THREADS - 1) / THREADS;
    bacon_forest_kernel<<<grid, THREADS>>>(c20, w_raw, out, B);
}

// round 4
// speedup vs baseline: 1.8275x; 1.5045x over previous
#include <cuda_runtime.h>

#define THREADS 128
#define SPT 2
#define SPB (THREADS * SPT)   // 256 samples per block

// Soft-tree node: w*min(a,b) + (1-w)*max(a,b) == max(a,b) - w*|a-b|
__device__ __forceinline__ float node(float a, float b, float w) {
    return fmaf(w, -fabsf(a - b), fmaxf(a, b));
}

__global__ void __launch_bounds__(THREADS)
bacon_forest_kernel(const float* __restrict__ c20,
                    const float* __restrict__ w_raw,
                    float* __restrict__ out,
                    int B)
{
    // sigmoid(w_raw); rows padded to 20 floats for LDS.128.
    __shared__ __align__(16) float sw[19 * 20];
    // One buffer, two lives: input stage (SPB*20), then output stage (SPB*19).
    __shared__ __align__(16) float buf[SPB * 20];

    const int tid = threadIdx.x;

    for (int i = tid; i < 19 * 20; i += THREADS) {
        int r = i / 20;
        int c = i - r * 20;
        float v = 0.0f;
        if (c < 19) {
            float raw = __ldg(&w_raw[r * 19 + c]);
            v = 1.0f / (1.0f + __expf(-raw));
        }
        sw[i] = v;
    }

    const int base = blockIdx.x * SPB;
    const int nS   = min(SPB, B - base);

    // Coalesced input staging: block's c20 region is contiguous, 16B-aligned.
    {
        const float4* g4 = reinterpret_cast<const float4*>(c20 + (size_t)base * 20);
        float4*       b4 = reinterpret_cast<float4*>(buf);
        const int nV = nS * 5;              // nS*20/4
        for (int i = tid; i < nV; i += THREADS)
            b4[i] = g4[i];
    }
    __syncthreads();

    // Two samples per thread: local ids tid and tid+THREADS.
    // Consume inputs immediately into tree-invariant (max, |diff|) pairs.
    float m[2][10], d[2][10];
    #pragma unroll
    for (int s = 0; s < 2; ++s) {
        const int l = tid + s * THREADS;    // l < SPB always: in-bounds smem read
        const float4* xp = reinterpret_cast<const float4*>(&buf[l * 20]);
        float4 q0 = xp[0], q1 = xp[1], q2 = xp[2], q3 = xp[3], q4 = xp[4];
        float x[20] = { q0.x, q0.y, q0.z, q0.w,  q1.x, q1.y, q1.z, q1.w,
                        q2.x, q2.y, q2.z, q2.w,  q3.x, q3.y, q3.z, q3.w,
                        q4.x, q4.y, q4.z, q4.w };
        #pragma unroll
        for (int j = 0; j < 10; ++j) {
            float a = x[2 * j], bb = x[2 * j + 1];
            m[s][j] = fmaxf(a, bb);
            d[s][j] = fabsf(a - bb);
        }
    }
    __syncthreads();    // all input reads done before buf is reused for outputs

    #pragma unroll 1
    for (int t = 0; t < 19; ++t) {
        // One tree's weights: 5x uniform LDS.128 (broadcast), shared by both samples.
        const float4* wp = reinterpret_cast<const float4*>(&sw[t * 20]);
        float4 w0 = wp[0], w1 = wp[1], w2 = wp[2], w3 = wp[3], w4 = wp[4];

        #pragma unroll
        for (int s = 0; s < 2; ++s) {
            // Layer 0 (20 -> 10): one FFMA per node from hoisted invariants.
            float y0 = fmaf(w0.x, -d[s][0], m[s][0]);
            float y1 = fmaf(w0.y, -d[s][1], m[s][1]);
            float y2 = fmaf(w0.z, -d[s][2], m[s][2]);
            float y3 = fmaf(w0.w, -d[s][3], m[s][3]);
            float y4 = fmaf(w1.x, -d[s][4], m[s][4]);
            float y5 = fmaf(w1.y, -d[s][5], m[s][5]);
            float y6 = fmaf(w1.z, -d[s][6], m[s][6]);
            float y7 = fmaf(w1.w, -d[s][7], m[s][7]);
            float y8 = fmaf(w2.x, -d[s][8], m[s][8]);
            float y9 = fmaf(w2.y, -d[s][9], m[s][9]);

            // Layer 1 (10 -> 5): cols 10..14
            float z0 = node(y0, y1, w2.z);
            float z1 = node(y2, y3, w2.w);
            float z2 = node(y4, y5, w3.x);
            float z3 = node(y6, y7, w3.y);
            float z4 = node(y8, y9, w3.z);

            // Layer 2 (5 -> 2, carry z4): cols 15,16
            float u0 = node(z0, z1, w3.w);
            float u1 = node(z2, z3, w4.x);

            // Layer 3 (3 -> 1, carry z4): col 17
            float v0 = node(u0, u1, w4.y);

            // Layer 4 (2 -> 1): col 18
            float o = node(v0, z4, w4.z);

            o = fminf(fmaxf(o, 1e-6f), 1.0f - 1e-6f);
            buf[(tid + s * THREADS) * 19 + t] = o;   // stride 19: STS conflict-free
        }
    }
    __syncthreads();

    // Coalesced writeback of nS*19 floats; base*19*4 bytes is 16B-aligned.
    const int nFlt = nS * 19;
    const int nVec = nFlt >> 2;
    float*        og = out + (size_t)base * 19;
    float4*       o4 = reinterpret_cast<float4*>(og);
    const float4* s4 = reinterpret_cast<const float4*>(buf);

    for (int i = tid; i < nVec; i += THREADS)
        o4[i] = s4[i];
    for (int i = (nVec << 2) + tid; i < nFlt; i += THREADS)
        og[i] = buf[i];
}

extern "C" void kernel_launch(void* const* d_in, const int* in_sizes, int n_in,
                              void* d_out, int out_size) {
    // metadata order: p1 (int32), p2 (int32), c20 (float32, B*20), w_raw (float32, 361)
    const float* c20   = (const float*)d_in[2];
    const float* w_raw = (const float*)d_in[3];
    float* out = (float*)d_out;
    int B = in_sizes[2] / 20;
    int grid = (B + SPB - 1) / SPB;
    bacon_forest_kernel<<<grid, THREADS>>>(c20, w_raw, out, B);
}

// round 5
// speedup vs baseline: 1.8938x; 1.0363x over previous
#include <cuda_runtime.h>
#include <cstdint>

#define THREADS 128
#define SPT 2
#define SPB (THREADS * SPT)   // 256 samples per block

// Packed fp32x2 FMA (sm_103a FFMA2) — only reachable via PTX.
#define FFMA2(D, A, B, C) \
    asm("fma.rn.f32x2 %0, %1, %2, %3;" : "=l"(D) : "l"(A), "l"(B), "l"(C))
#define PACK2(D, LO, HI) \
    asm("mov.b64 %0, {%1, %2};" : "=l"(D) : "f"(LO), "f"(HI))
#define UNPACK2(LO, HI, S) \
    asm("mov.b64 {%0, %1}, %2;" : "=f"(LO), "=f"(HI) : "l"(S))

// Soft-tree node: w*min + (1-w)*max == max - w*|a-b|  (FADD+FMNMX+FFMA)
__device__ __forceinline__ float node(float a, float b, float w) {
    return fmaf(w, -fabsf(a - b), fmaxf(a, b));
}

__global__ void __launch_bounds__(THREADS)
bacon_forest_kernel(const float* __restrict__ c20,
                    const float* __restrict__ w_raw,
                    float* __restrict__ out,
                    int B)
{
    // Layer-0 weights, NEGATED and DUPLICATED: dw0[t][j] = (-w, -w).
    // Row = 10 float2 = 80B (16B-aligned) -> 5x LDS.128 gives packed u64 pairs.
    __shared__ __align__(16) float2 dw0[19 * 10];
    // Upper weights (cols 10..18) padded to 12 floats/row -> 3x LDS.128.
    __shared__ __align__(16) float swu[19 * 12];
    // One buffer, two lives: input stage (SPB*20), then output stage (SPB*19).
    __shared__ __align__(16) float buf[SPB * 20];

    const int tid = threadIdx.x;

    for (int i = tid; i < 19 * 19; i += THREADS) {
        int r = i / 19;
        int c = i - r * 19;
        float raw = __ldg(&w_raw[i]);
        float s = 1.0f / (1.0f + __expf(-raw));
        if (c < 10) dw0[r * 10 + c] = make_float2(-s, -s);
        else        swu[r * 12 + (c - 10)] = s;
    }
    // zero the swu pad lanes (9..11) so LDS.128 reads defined data
    for (int i = tid; i < 19 * 3; i += THREADS) {
        int r = i / 3;
        swu[r * 12 + 9 + (i - r * 3)] = 0.0f;
    }

    const int base = blockIdx.x * SPB;
    const int nS   = min(SPB, B - base);

    // Coalesced input staging (block region contiguous, 16B-aligned).
    {
        const float4* g4 = reinterpret_cast<const float4*>(c20 + (size_t)base * 20);
        float4*       b4 = reinterpret_cast<float4*>(buf);
        const int nV = nS * 5;
        for (int i = tid; i < nV; i += THREADS)
            b4[i] = g4[i];
    }
    __syncthreads();

    // Per-thread samples s0=tid, s1=tid+THREADS. Build packed tree-invariants:
    // m2[j] = (max_s0, max_s1), ad2[j] = (|a-b|_s0, |a-b|_s1).
    uint64_t m2[10], ad2[10];
    {
        float mx[2][10], ad[2][10];
        #pragma unroll
        for (int s = 0; s < 2; ++s) {
            const float4* xp = reinterpret_cast<const float4*>(&buf[(tid + s * THREADS) * 20]);
            float4 q0 = xp[0], q1 = xp[1], q2 = xp[2], q3 = xp[3], q4 = xp[4];
            float x[20] = { q0.x, q0.y, q0.z, q0.w,  q1.x, q1.y, q1.z, q1.w,
                            q2.x, q2.y, q2.z, q2.w,  q3.x, q3.y, q3.z, q3.w,
                            q4.x, q4.y, q4.z, q4.w };
            #pragma unroll
            for (int j = 0; j < 10; ++j) {
                float a = x[2 * j], b = x[2 * j + 1];
                mx[s][j] = fmaxf(a, b);
                ad[s][j] = fabsf(a - b);
            }
        }
        #pragma unroll
        for (int j = 0; j < 10; ++j) {
            PACK2(m2[j],  mx[0][j], mx[1][j]);
            PACK2(ad2[j], ad[0][j], ad[1][j]);
        }
    }
    __syncthreads();    // input reads done before buf is reused for outputs

    #pragma unroll
    for (int t = 0; t < 19; ++t) {
        // Layer-0 weights: 5x LDS.128 -> 10 packed (-w,-w) u64s, no pack instrs.
        const ulonglong2* dwp = reinterpret_cast<const ulonglong2*>(&dw0[t * 10]);
        ulonglong2 P0 = dwp[0], P1 = dwp[1], P2 = dwp[2], P3 = dwp[3], P4 = dwp[4];
        // Upper weights cols 10..18: 3x LDS.128.
        const float4* up = reinterpret_cast<const float4*>(&swu[t * 12]);
        float4 u0 = up[0], u1 = up[1], u2 = up[2];

        // Layer 0 (20 -> 10), both samples per instruction: y2 = fma2(-w, |d|, max)
        uint64_t Y[10];
        FFMA2(Y[0], P0.x, ad2[0], m2[0]);
        FFMA2(Y[1], P0.y, ad2[1], m2[1]);
        FFMA2(Y[2], P1.x, ad2[2], m2[2]);
        FFMA2(Y[3], P1.y, ad2[3], m2[3]);
        FFMA2(Y[4], P2.x, ad2[4], m2[4]);
        FFMA2(Y[5], P2.y, ad2[5], m2[5]);
        FFMA2(Y[6], P3.x, ad2[6], m2[6]);
        FFMA2(Y[7], P3.y, ad2[7], m2[7]);
        FFMA2(Y[8], P4.x, ad2[8], m2[8]);
        FFMA2(Y[9], P4.y, ad2[9], m2[9]);

        #pragma unroll
        for (int s = 0; s < 2; ++s) {
            float y0, y1, y2, y3, y4, y5, y6, y7, y8, y9, dead;
            if (s == 0) {
                UNPACK2(y0, dead, Y[0]); UNPACK2(y1, dead, Y[1]);
                UNPACK2(y2, dead, Y[2]); UNPACK2(y3, dead, Y[3]);
                UNPACK2(y4, dead, Y[4]); UNPACK2(y5, dead, Y[5]);
                UNPACK2(y6, dead, Y[6]); UNPACK2(y7, dead, Y[7]);
                UNPACK2(y8, dead, Y[8]); UNPACK2(y9, dead, Y[9]);
            } else {
                UNPACK2(dead, y0, Y[0]); UNPACK2(dead, y1, Y[1]);
                UNPACK2(dead, y2, Y[2]); UNPACK2(dead, y3, Y[3]);
                UNPACK2(dead, y4, Y[4]); UNPACK2(dead, y5, Y[5]);
                UNPACK2(dead, y6, Y[6]); UNPACK2(dead, y7, Y[7]);
                UNPACK2(dead, y8, Y[8]); UNPACK2(dead, y9, Y[9]);
            }

            // Layer 1 (10 -> 5): cols 10..14
            float z0 = node(y0, y1, u0.x);
            float z1 = node(y2, y3, u0.y);
            float z2 = node(y4, y5, u0.z);
            float z3 = node(y6, y7, u0.w);
            float z4 = node(y8, y9, u1.x);

            // Layer 2 (5 -> 2, carry z4): cols 15,16
            float v0 = node(z0, z1, u1.y);
            float v1 = node(z2, z3, u1.z);

            // Layer 3 (3 -> 1, carry z4): col 17
            float r0 = node(v0, v1, u1.w);

            // Layer 4 (2 -> 1): col 18
            float o = node(r0, z4, u2.x);

            o = fminf(fmaxf(o, 1e-6f), 1.0f - 1e-6f);
            buf[(tid + s * THREADS) * 19 + t] = o;   // stride 19: conflict-free
        }
    }
    __syncthreads();

    // Coalesced writeback of nS*19 floats (base*19 is 16B-aligned).
    const int nFlt = nS * 19;
    const int nVec = nFlt >> 2;
    float*        og = out + (size_t)base * 19;
    float4*       o4 = reinterpret_cast<float4*>(og);
    const float4* s4 = reinterpret_cast<const float4*>(buf);

    for (int i = tid; i < nVec; i += THREADS)
        o4[i] = s4[i];
    for (int i = (nVec << 2) + tid; i < nFlt; i += THREADS)
        og[i] = buf[i];
}

extern "C" void kernel_launch(void* const* d_in, const int* in_sizes, int n_in,
                              void* d_out, int out_size) {
    // metadata order: p1 (int32), p2 (int32), c20 (float32, B*20), w_raw (float32, 361)
    const float* c20   = (const float*)d_in[2];
    const float* w_raw = (const float*)d_in[3];
    float* out = (float*)d_out;
    int B = in_sizes[2] / 20;
    int grid = (B + SPB - 1) / SPB;
    bacon_forest_kernel<<<grid, THREADS>>>(c20, w_raw, out, B);
}